// round 1
// baseline (speedup 1.0000x reference)
#include <cuda_runtime.h>
#include <cstdint>

#define T_ 8192
#define D_ 1024
#define H_ 1024
#define E_ 8
#define B_ 4
#define S_ 2048

#define BM 64
#define BN 64
#define BK 16

// ---------------- scratch (no allocation allowed) ----------------
__device__ int g_cnt[E_];
__device__ int g_base[E_];
__device__ int g_btok[E_ * T_];
__device__ float g_bwt[E_ * T_];
__device__ unsigned char g_nonpad[T_];
__device__ float g_invcnt[B_];
__device__ float g_mean[E_ * B_ * D_];
__device__ float g_hact[(size_t)2 * T_ * H_];   // 64 MB: one row per selected (token,expert) pair

// ---------------- f32x2 helpers ----------------
__device__ __forceinline__ unsigned long long packff(float v) {
    unsigned int u = __float_as_uint(v);
    unsigned long long r;
    asm("mov.b64 %0, {%1, %1};" : "=l"(r) : "r"(u));
    return r;
}
__device__ __forceinline__ float2 unpk(unsigned long long v) {
    unsigned int lo, hi;
    asm("mov.b64 {%0, %1}, %2;" : "=r"(lo), "=r"(hi) : "l"(v));
    return make_float2(__uint_as_float(lo), __uint_as_float(hi));
}
__device__ __forceinline__ void ffma2(unsigned long long& d,
                                      unsigned long long a,
                                      unsigned long long b) {
    asm("fma.rn.f32x2 %0, %1, %2, %3;" : "=l"(d) : "l"(a), "l"(b), "l"(d));
}

// ---------------- prep: mask decode + zeroing ----------------
__global__ void prep_kernel(const unsigned char* __restrict__ pad,
                            const unsigned char* __restrict__ mid) {
    __shared__ int onebyte;
    __shared__ int cnts[B_];
    int tid = threadIdx.x;
    if (tid == 0) onebyte = 0;
    if (tid < B_) cnts[tid] = 0;
    if (tid < E_) g_cnt[tid] = 0;
    __syncthreads();
    // Detect element width: if elements are 4-byte (int32 0/1 or float 0.0/1.0),
    // every byte at offset 4t+1 is zero. If 1-byte bools, ~30% of those bytes are 1.
    int found = 0;
    for (int i = tid; i < 2048; i += 256)
        if (pad[4 * i + 1]) found = 1;
    if (found) onebyte = 1;
    __syncthreads();
    bool b1 = (onebyte != 0);
    const unsigned int* pw = (const unsigned int*)pad;
    const unsigned int* mw = (const unsigned int*)mid;
    for (int t = tid; t < T_; t += 256) {
        bool p = b1 ? (pad[t] != 0) : (pw[t] != 0);
        bool m = b1 ? (mid[t] != 0) : (mw[t] != 0);
        unsigned char np = (!p && !m) ? 1 : 0;
        g_nonpad[t] = np;
        if (np) atomicAdd(&cnts[t >> 11], 1);
    }
    for (int i = tid; i < E_ * B_ * D_; i += 256) g_mean[i] = 0.f;
    __syncthreads();
    if (tid < B_) g_invcnt[tid] = 1.f / (float)cnts[tid];
}

// ---------------- gating: softmax + top-2 + bucket scatter ----------------
__global__ void gate_kernel(const float* __restrict__ x,
                            const float* __restrict__ gw,
                            float* __restrict__ route_out) {
    int warp = threadIdx.x >> 5, lane = threadIdx.x & 31;
    int t = blockIdx.x * 8 + warp;
    const float* xr = x + (size_t)t * D_;
    float acc[8];
#pragma unroll
    for (int e = 0; e < 8; e++) acc[e] = 0.f;
    for (int d = lane; d < D_; d += 32) {
        float xv = xr[d];
        float4 g0 = *(const float4*)(gw + (size_t)d * 8);
        float4 g1 = *(const float4*)(gw + (size_t)d * 8 + 4);
        acc[0] += xv * g0.x; acc[1] += xv * g0.y;
        acc[2] += xv * g0.z; acc[3] += xv * g0.w;
        acc[4] += xv * g1.x; acc[5] += xv * g1.y;
        acc[6] += xv * g1.z; acc[7] += xv * g1.w;
    }
#pragma unroll
    for (int o = 16; o; o >>= 1)
#pragma unroll
        for (int e = 0; e < 8; e++)
            acc[e] += __shfl_xor_sync(0xffffffffu, acc[e], o);
    if (lane == 0) {
        float mx = acc[0];
#pragma unroll
        for (int e = 1; e < 8; e++) mx = fmaxf(mx, acc[e]);
        float p[8], s = 0.f;
#pragma unroll
        for (int e = 0; e < 8; e++) { p[e] = __expf(acc[e] - mx); s += p[e]; }
        float inv = 1.f / s;
#pragma unroll
        for (int e = 0; e < 8; e++) p[e] *= inv;
        float* ro = route_out + (size_t)t * 8;
#pragma unroll
        for (int e = 0; e < 8; e++) ro[e] = p[e];
        // top-2 (ties -> lowest index, matching jax.lax.top_k)
        int e0 = 0;
#pragma unroll
        for (int e = 1; e < 8; e++) if (p[e] > p[e0]) e0 = e;
        int e1 = (e0 == 0) ? 1 : 0;
#pragma unroll
        for (int e = 0; e < 8; e++) if (e != e0 && p[e] > p[e1]) e1 = e;
        float inv2 = 1.f / (p[e0] + p[e1]);
        int s0 = atomicAdd(&g_cnt[e0], 1);
        g_btok[e0 * T_ + s0] = t; g_bwt[e0 * T_ + s0] = p[e0] * inv2;
        int s1 = atomicAdd(&g_cnt[e1], 1);
        g_btok[e1 * T_ + s1] = t; g_bwt[e1 * T_ + s1] = p[e1] * inv2;
    }
}

__global__ void scan_kernel() {
    if (threadIdx.x == 0) {
        int acc = 0;
        for (int e = 0; e < E_; e++) { g_base[e] = acc; acc += g_cnt[e]; }
    }
}

// ---------------- stage A: hact = silu(X@w1) * (X@w3), grouped by expert ----------------
__global__ __launch_bounds__(256, 1) void ffn1_kernel(const float* __restrict__ x,
                                                      const float* __restrict__ w1,
                                                      const float* __restrict__ w3) {
    int e = blockIdx.y >> 7;
    int mt = blockIdx.y & 127;
    int cnt = g_cnt[e];
    int row0 = mt * BM;
    if (row0 >= cnt) return;
    int rows = min(BM, cnt - row0);
    int n0 = blockIdx.x * BN;

    __shared__ __align__(16) float Xs[BK][BM];
    __shared__ __align__(16) float W1s[BK][BN];
    __shared__ __align__(16) float W3s[BK][BN];
    __shared__ int toks[BM];

    int tid = threadIdx.x;
    if (tid < BM)
        toks[tid] = (tid < rows) ? g_btok[e * T_ + row0 + tid] : g_btok[e * T_ + row0];
    __syncthreads();

    int ty = tid >> 4, tx = tid & 15;
    unsigned long long acc1[4][2], acc3[4][2];
#pragma unroll
    for (int i = 0; i < 4; i++) {
        acc1[i][0] = 0ULL; acc1[i][1] = 0ULL;
        acc3[i][0] = 0ULL; acc3[i][1] = 0ULL;
    }

    int lr = tid >> 2;
    int lk = (tid & 3) * 4;
    const float* xrow = x + (size_t)toks[lr] * D_ + lk;
    int wr = tid >> 4;
    int wc = (tid & 15) * 4;
    const float* w1p = w1 + (size_t)e * D_ * H_ + (size_t)wr * H_ + n0 + wc;
    const float* w3p = w3 + (size_t)e * D_ * H_ + (size_t)wr * H_ + n0 + wc;

    for (int k0 = 0; k0 < D_; k0 += BK) {
        float4 xv = *(const float4*)(xrow + k0);
        Xs[lk + 0][lr] = xv.x; Xs[lk + 1][lr] = xv.y;
        Xs[lk + 2][lr] = xv.z; Xs[lk + 3][lr] = xv.w;
        *(float4*)&W1s[wr][wc] = *(const float4*)(w1p + (size_t)k0 * H_);
        *(float4*)&W3s[wr][wc] = *(const float4*)(w3p + (size_t)k0 * H_);
        __syncthreads();
#pragma unroll
        for (int kk = 0; kk < BK; kk++) {
            float4 a = *(const float4*)&Xs[kk][ty * 4];
            unsigned long long aa[4];
            aa[0] = packff(a.x); aa[1] = packff(a.y);
            aa[2] = packff(a.z); aa[3] = packff(a.w);
            ulonglong2 b1 = *(const ulonglong2*)&W1s[kk][tx * 4];
            ulonglong2 b3 = *(const ulonglong2*)&W3s[kk][tx * 4];
#pragma unroll
            for (int i = 0; i < 4; i++) {
                ffma2(acc1[i][0], aa[i], b1.x);
                ffma2(acc1[i][1], aa[i], b1.y);
                ffma2(acc3[i][0], aa[i], b3.x);
                ffma2(acc3[i][1], aa[i], b3.y);
            }
        }
        __syncthreads();
    }

    int gbase = g_base[e] + row0;
#pragma unroll
    for (int i = 0; i < 4; i++) {
        int r = ty * 4 + i;
        if (r < rows) {
            float* out = g_hact + (size_t)(gbase + r) * H_ + n0 + tx * 4;
            float2 h10 = unpk(acc1[i][0]);
            float2 h11 = unpk(acc1[i][1]);
            float2 h30 = unpk(acc3[i][0]);
            float2 h31 = unpk(acc3[i][1]);
            float4 o;
            o.x = h10.x / (1.f + __expf(-h10.x)) * h30.x;
            o.y = h10.y / (1.f + __expf(-h10.y)) * h30.y;
            o.z = h11.x / (1.f + __expf(-h11.x)) * h31.x;
            o.w = h11.y / (1.f + __expf(-h11.y)) * h31.y;
            *(float4*)out = o;
        }
    }
}

// ---------------- stage B: Y = hact @ w2, scatter with combine weights ----------------
__global__ __launch_bounds__(256, 1) void ffn2_kernel(const float* __restrict__ w2,
                                                      float* __restrict__ outF) {
    int e = blockIdx.y >> 7;
    int mt = blockIdx.y & 127;
    int cnt = g_cnt[e];
    int row0 = mt * BM;
    if (row0 >= cnt) return;
    int rows = min(BM, cnt - row0);
    int n0 = blockIdx.x * BN;

    __shared__ __align__(16) float Hs[BK][BM];
    __shared__ __align__(16) float W2s[BK][BN];
    __shared__ int toks[BM];
    __shared__ float wts[BM];

    int tid = threadIdx.x;
    if (tid < BM) {
        int idx = e * T_ + row0 + tid;
        toks[tid] = (tid < rows) ? g_btok[idx] : 0;
        wts[tid] = (tid < rows) ? g_bwt[idx] : 0.f;
    }
    __syncthreads();

    int ty = tid >> 4, tx = tid & 15;
    unsigned long long acc[4][2];
#pragma unroll
    for (int i = 0; i < 4; i++) { acc[i][0] = 0ULL; acc[i][1] = 0ULL; }

    int lr = tid >> 2;
    int lk = (tid & 3) * 4;
    int gbase = g_base[e] + row0;
    const float* hrow = g_hact + (size_t)(gbase + min(lr, rows - 1)) * H_ + lk;
    int wr = tid >> 4;
    int wc = (tid & 15) * 4;
    const float* w2p = w2 + (size_t)e * H_ * D_ + (size_t)wr * D_ + n0 + wc;

    for (int k0 = 0; k0 < H_; k0 += BK) {
        float4 hv = *(const float4*)(hrow + k0);
        Hs[lk + 0][lr] = hv.x; Hs[lk + 1][lr] = hv.y;
        Hs[lk + 2][lr] = hv.z; Hs[lk + 3][lr] = hv.w;
        *(float4*)&W2s[wr][wc] = *(const float4*)(w2p + (size_t)k0 * D_);
        __syncthreads();
#pragma unroll
        for (int kk = 0; kk < BK; kk++) {
            float4 a = *(const float4*)&Hs[kk][ty * 4];
            unsigned long long aa[4];
            aa[0] = packff(a.x); aa[1] = packff(a.y);
            aa[2] = packff(a.z); aa[3] = packff(a.w);
            ulonglong2 b = *(const ulonglong2*)&W2s[kk][tx * 4];
#pragma unroll
            for (int i = 0; i < 4; i++) {
                ffma2(acc[i][0], aa[i], b.x);
                ffma2(acc[i][1], aa[i], b.y);
            }
        }
        __syncthreads();
    }

#pragma unroll
    for (int i = 0; i < 4; i++) {
        int r = ty * 4 + i;
        if (r < rows) {
            int t = toks[r];
            float wt = wts[r];
            int bb = t >> 11;
            bool np = (g_nonpad[t] != 0);
            float* fo = outF + (size_t)t * D_ + n0 + tx * 4;
            float* mp = g_mean + (size_t)(e * B_ + bb) * D_ + n0 + tx * 4;
            float2 y0 = unpk(acc[i][0]);
            float2 y1 = unpk(acc[i][1]);
            float c0 = wt * y0.x, c1 = wt * y0.y, c2 = wt * y1.x, c3 = wt * y1.y;
            atomicAdd(fo + 0, c0); atomicAdd(fo + 1, c1);
            atomicAdd(fo + 2, c2); atomicAdd(fo + 3, c3);
            if (np) {
                atomicAdd(mp + 0, c0); atomicAdd(mp + 1, c1);
                atomicAdd(mp + 2, c2); atomicAdd(mp + 3, c3);
            }
        }
    }
}

// ---------------- classifier: cumulative per-expert logits ----------------
__global__ void clf_kernel(const float* __restrict__ clf_w,
                           const float* __restrict__ clf_b,
                           float* __restrict__ outL) {
    __shared__ float dots[32];
    int w = threadIdx.x >> 5, lane = threadIdx.x & 31;
    const float* m = g_mean + (size_t)w * D_;
    float s = 0.f;
    for (int d = lane; d < D_; d += 32) s += m[d] * clf_w[d];
#pragma unroll
    for (int o = 16; o; o >>= 1) s += __shfl_xor_sync(0xffffffffu, s, o);
    if (lane == 0) dots[w] = s;
    __syncthreads();
    if (threadIdx.x < 32) {
        int e = threadIdx.x >> 2, b = threadIdx.x & 3;
        float c = 0.f;
        for (int ee = 0; ee <= e; ee++) c += dots[ee * 4 + b];
        outL[e * B_ + b] = c * g_invcnt[b] + clf_b[0];
    }
}

// ---------------- launch ----------------
extern "C" void kernel_launch(void* const* d_in, const int* in_sizes, int n_in,
                              void* d_out, int out_size) {
    // Input order: x, tgt_pad, tgt_mask_id_bool, [top_k], gate_w, w1, w2, w3, clf_w, clf_b
    int base = 4;
    if (n_in == 9 || in_sizes[3] != 1) base = 3;  // top_k dropped by harness
    const float* x = (const float*)d_in[0];
    const unsigned char* pad = (const unsigned char*)d_in[1];
    const unsigned char* mid = (const unsigned char*)d_in[2];
    const float* gw = (const float*)d_in[base + 0];
    const float* w1 = (const float*)d_in[base + 1];
    const float* w2 = (const float*)d_in[base + 2];
    const float* w3 = (const float*)d_in[base + 3];
    const float* cw = (const float*)d_in[base + 4];
    const float* cb = (const float*)d_in[base + 5];
    float* out = (float*)d_out;

    float* out_final = out;                                  // [T, D]
    float* out_logits = out + (size_t)T_ * D_;               // [E, B, 1]
    float* out_route = out + (size_t)T_ * D_ + E_ * B_;      // [B, S, E]

    cudaMemsetAsync(out_final, 0, (size_t)T_ * D_ * sizeof(float), 0);
    prep_kernel<<<1, 256>>>(pad, mid);
    gate_kernel<<<T_ / 8, 256>>>(x, gw, out_route);
    scan_kernel<<<1, 32>>>();
    dim3 grid(H_ / BN, E_ * (T_ / BM));
    ffn1_kernel<<<grid, 256>>>(x, w1, w3);
    ffn2_kernel<<<grid, 256>>>(w2, out_final);
    clf_kernel<<<1, 1024>>>(cw, cb, out_logits);
}

// round 4
// speedup vs baseline: 2.4830x; 2.4830x over previous
#include <cuda_runtime.h>
#include <cstdint>

#define T_ 8192
#define D_ 1024
#define H_ 1024
#define E_ 8
#define B_ 4
#define S_ 2048

#define BM 128

// ---------------- scratch (no allocation allowed) ----------------
__device__ int g_cnt[E_];
__device__ int g_base[E_];
__device__ int g_btok[E_ * T_];
__device__ float g_bwt[E_ * T_];
__device__ unsigned char g_nonpad[T_];
__device__ float g_invcnt[B_];
__device__ float g_mean[E_ * B_ * D_];
__device__ float g_hact[(size_t)2 * T_ * H_];   // 64 MB

// ================= helpers =================
__device__ __forceinline__ uint32_t smem_u32(const void* p) {
    uint32_t a;
    asm("{ .reg .u64 t; cvta.to.shared.u64 t, %1; cvt.u32.u64 %0, t; }" : "=r"(a) : "l"(p));
    return a;
}
__device__ __forceinline__ void sts128u(uint32_t a, uint32_t x, uint32_t y, uint32_t z, uint32_t w) {
    asm volatile("st.shared.v4.b32 [%0], {%1,%2,%3,%4};" :: "r"(a), "r"(x), "r"(y), "r"(z), "r"(w));
}
// split f32 pair -> packed bf16 hi + bf16 lo  (lower half = first element)
__device__ __forceinline__ void cvt2(float f0, float f1, uint32_t& hi, uint32_t& lo) {
    asm("cvt.rn.bf16x2.f32 %0, %1, %2;" : "=r"(hi) : "f"(f1), "f"(f0));
    float f0h = __uint_as_float(hi << 16);
    float f1h = __uint_as_float(hi & 0xffff0000u);
    asm("cvt.rn.bf16x2.f32 %0, %1, %2;" : "=r"(lo) : "f"(f1 - f1h), "f"(f0 - f0h));
}
__device__ __forceinline__ void ldsm4(uint32_t* r, uint32_t a) {
    asm volatile("ldmatrix.sync.aligned.m8n8.x4.shared.b16 {%0,%1,%2,%3}, [%4];"
                 : "=r"(r[0]), "=r"(r[1]), "=r"(r[2]), "=r"(r[3]) : "r"(a));
}
__device__ __forceinline__ void ldsm4t(uint32_t* r, uint32_t a) {
    asm volatile("ldmatrix.sync.aligned.m8n8.x4.trans.shared.b16 {%0,%1,%2,%3}, [%4];"
                 : "=r"(r[0]), "=r"(r[1]), "=r"(r[2]), "=r"(r[3]) : "r"(a));
}
__device__ __forceinline__ void mma16816(float* d, const uint32_t* a, uint32_t b0, uint32_t b1) {
    asm volatile(
        "mma.sync.aligned.m16n8k16.row.col.f32.bf16.bf16.f32 "
        "{%0,%1,%2,%3},{%4,%5,%6,%7},{%8,%9},{%0,%1,%2,%3};"
        : "+f"(d[0]), "+f"(d[1]), "+f"(d[2]), "+f"(d[3])
        : "r"(a[0]), "r"(a[1]), "r"(a[2]), "r"(a[3]), "r"(b0), "r"(b1));
}
// swizzled byte offset, 128B rows (8 x 16B units)
__device__ __forceinline__ uint32_t off128(int r, int u) {
    return (uint32_t)(r * 128 + ((u ^ (r & 7)) << 4));
}
// swizzled byte offset, 256B rows (16 units; swizzle low 3 bits only)
__device__ __forceinline__ uint32_t off256(int r, int u) {
    return (uint32_t)(r * 256 + ((((u ^ r) & 7) | (u & 8)) << 4));
}

// ---------------- prep ----------------
__global__ void prep_kernel(const unsigned char* __restrict__ pad,
                            const unsigned char* __restrict__ mid) {
    __shared__ int onebyte;
    __shared__ int cnts[B_];
    int tid = threadIdx.x;
    if (tid == 0) onebyte = 0;
    if (tid < B_) cnts[tid] = 0;
    if (tid < E_) g_cnt[tid] = 0;
    __syncthreads();
    int found = 0;
    for (int i = tid; i < 2048; i += 256)
        if (pad[4 * i + 1]) found = 1;
    if (found) onebyte = 1;
    __syncthreads();
    bool b1 = (onebyte != 0);
    const unsigned int* pw = (const unsigned int*)pad;
    const unsigned int* mw = (const unsigned int*)mid;
    for (int t = tid; t < T_; t += 256) {
        bool p = b1 ? (pad[t] != 0) : (pw[t] != 0);
        bool m = b1 ? (mid[t] != 0) : (mw[t] != 0);
        unsigned char np = (!p && !m) ? 1 : 0;
        g_nonpad[t] = np;
        if (np) atomicAdd(&cnts[t >> 11], 1);
    }
    for (int i = tid; i < E_ * B_ * D_; i += 256) g_mean[i] = 0.f;
    __syncthreads();
    if (tid < B_) g_invcnt[tid] = 1.f / (float)cnts[tid];
}

// ---------------- gating ----------------
__global__ void gate_kernel(const float* __restrict__ x,
                            const float* __restrict__ gw,
                            float* __restrict__ route_out) {
    int warp = threadIdx.x >> 5, lane = threadIdx.x & 31;
    int t = blockIdx.x * 8 + warp;
    const float* xr = x + (size_t)t * D_;
    float acc[8];
#pragma unroll
    for (int e = 0; e < 8; e++) acc[e] = 0.f;
    for (int d = lane; d < D_; d += 32) {
        float xv = xr[d];
        float4 g0 = *(const float4*)(gw + (size_t)d * 8);
        float4 g1 = *(const float4*)(gw + (size_t)d * 8 + 4);
        acc[0] += xv * g0.x; acc[1] += xv * g0.y;
        acc[2] += xv * g0.z; acc[3] += xv * g0.w;
        acc[4] += xv * g1.x; acc[5] += xv * g1.y;
        acc[6] += xv * g1.z; acc[7] += xv * g1.w;
    }
#pragma unroll
    for (int o = 16; o; o >>= 1)
#pragma unroll
        for (int e = 0; e < 8; e++)
            acc[e] += __shfl_xor_sync(0xffffffffu, acc[e], o);
    if (lane == 0) {
        float mx = acc[0];
#pragma unroll
        for (int e = 1; e < 8; e++) mx = fmaxf(mx, acc[e]);
        float p[8], s = 0.f;
#pragma unroll
        for (int e = 0; e < 8; e++) { p[e] = __expf(acc[e] - mx); s += p[e]; }
        float inv = 1.f / s;
#pragma unroll
        for (int e = 0; e < 8; e++) p[e] *= inv;
        float* ro = route_out + (size_t)t * 8;
#pragma unroll
        for (int e = 0; e < 8; e++) ro[e] = p[e];
        int e0 = 0;
#pragma unroll
        for (int e = 1; e < 8; e++) if (p[e] > p[e0]) e0 = e;
        int e1 = (e0 == 0) ? 1 : 0;
#pragma unroll
        for (int e = 0; e < 8; e++) if (e != e0 && p[e] > p[e1]) e1 = e;
        float inv2 = 1.f / (p[e0] + p[e1]);
        int s0 = atomicAdd(&g_cnt[e0], 1);
        g_btok[e0 * T_ + s0] = t; g_bwt[e0 * T_ + s0] = p[e0] * inv2;
        int s1 = atomicAdd(&g_cnt[e1], 1);
        g_btok[e1 * T_ + s1] = t; g_bwt[e1 * T_ + s1] = p[e1] * inv2;
    }
}

__global__ void scan_kernel() {
    if (threadIdx.x == 0) {
        int acc = 0;
        for (int e = 0; e < E_; e++) { g_base[e] = acc; acc += g_cnt[e]; }
    }
}

// ============ ffn1: hact = silu(X@w1)*(X@w3), bf16 3-split mma.sync ============
// CTA: M=128, N=64 (w1) + same 64 cols of w3. 8 warps = 4(M) x 2(N-half 32).
__global__ __launch_bounds__(256, 1) void ffn1_mma(const float* __restrict__ x,
                                                   const float* __restrict__ w1,
                                                   const float* __restrict__ w3) {
    extern __shared__ char dyn[];
    __shared__ int toks[BM];
    int e = blockIdx.y >> 6, mt = blockIdx.y & 63;
    int cnt = g_cnt[e];
    int row0 = mt * BM;
    if (row0 >= cnt) return;
    int rows = min(BM, cnt - row0);
    int n0 = blockIdx.x * 64;
    int tid = threadIdx.x, wid = tid >> 5, lane = tid & 31;
    if (tid < BM)
        toks[tid] = (tid < rows) ? g_btok[e * T_ + row0 + tid] : g_btok[e * T_ + row0];
    __syncthreads();
    uint32_t sb = (smem_u32(dyn) + 1023u) & ~1023u;

    // producer mapping
    int am = tid >> 1, ak = (tid & 1) * 16;
    const float* ap = x + (size_t)toks[am] * D_ + ak;
    int bkr = tid >> 3, bnc = (tid & 7) * 8;
    const float* p1 = w1 + (size_t)e * D_ * H_ + (size_t)bkr * H_ + n0 + bnc;
    const float* p3 = w3 + (size_t)e * D_ * H_ + (size_t)bkr * H_ + n0 + bnc;

    float4 ra[4], r1[2], r3[2];
#pragma unroll
    for (int j = 0; j < 4; j++) ra[j] = *(const float4*)(ap + j * 4);
#pragma unroll
    for (int j = 0; j < 2; j++) {
        r1[j] = *(const float4*)(p1 + j * 4);
        r3[j] = *(const float4*)(p3 + j * 4);
    }

    float acc1[2][4][4], acc3[2][4][4];
#pragma unroll
    for (int a = 0; a < 2; a++)
#pragma unroll
        for (int b = 0; b < 4; b++)
#pragma unroll
            for (int q = 0; q < 4; q++) { acc1[a][b][q] = 0.f; acc3[a][b][q] = 0.f; }

    int lr = (lane & 7) + ((lane >> 3) & 1) * 8;
    int uo = (lane >> 4) & 1;
    int mq = wid & 3, nh = wid >> 2;

    for (int c = 0; c < 32; c++) {
        uint32_t base = sb + (uint32_t)(c & 1) * 32768u;
        uint32_t aT = base, b1h = base + 16384u, b1l = base + 20480u;
        uint32_t b3h = base + 24576u, b3l = base + 28672u;
        // A: 16 elems of row am
        {
            uint32_t h[8], l[8];
            cvt2(ra[0].x, ra[0].y, h[0], l[0]); cvt2(ra[0].z, ra[0].w, h[1], l[1]);
            cvt2(ra[1].x, ra[1].y, h[2], l[2]); cvt2(ra[1].z, ra[1].w, h[3], l[3]);
            cvt2(ra[2].x, ra[2].y, h[4], l[4]); cvt2(ra[2].z, ra[2].w, h[5], l[5]);
            cvt2(ra[3].x, ra[3].y, h[6], l[6]); cvt2(ra[3].z, ra[3].w, h[7], l[7]);
            int u0 = ak >> 3;
            sts128u(aT + off128(am, u0),     h[0], h[1], h[2], h[3]);
            sts128u(aT + off128(am, u0 + 1), h[4], h[5], h[6], h[7]);
            sts128u(aT + off128(am, u0 + 4), l[0], l[1], l[2], l[3]);
            sts128u(aT + off128(am, u0 + 5), l[4], l[5], l[6], l[7]);
        }
        // B: 8 n's of k-row bkr, both matrices
        {
            uint32_t h[4], l[4];
            int u = bnc >> 3;
            cvt2(r1[0].x, r1[0].y, h[0], l[0]); cvt2(r1[0].z, r1[0].w, h[1], l[1]);
            cvt2(r1[1].x, r1[1].y, h[2], l[2]); cvt2(r1[1].z, r1[1].w, h[3], l[3]);
            sts128u(b1h + off128(bkr, u), h[0], h[1], h[2], h[3]);
            sts128u(b1l + off128(bkr, u), l[0], l[1], l[2], l[3]);
            cvt2(r3[0].x, r3[0].y, h[0], l[0]); cvt2(r3[0].z, r3[0].w, h[1], l[1]);
            cvt2(r3[1].x, r3[1].y, h[2], l[2]); cvt2(r3[1].z, r3[1].w, h[3], l[3]);
            sts128u(b3h + off128(bkr, u), h[0], h[1], h[2], h[3]);
            sts128u(b3l + off128(bkr, u), l[0], l[1], l[2], l[3]);
        }
        __syncthreads();
        if (c + 1 < 32) {
            const float* apn = ap + (c + 1) * 32;
#pragma unroll
            for (int j = 0; j < 4; j++) ra[j] = *(const float4*)(apn + j * 4);
            const float* q1 = p1 + (size_t)(c + 1) * 32 * H_;
            const float* q3 = p3 + (size_t)(c + 1) * 32 * H_;
#pragma unroll
            for (int j = 0; j < 2; j++) {
                r1[j] = *(const float4*)(q1 + j * 4);
                r3[j] = *(const float4*)(q3 + j * 4);
            }
        }
#pragma unroll
        for (int kb = 0; kb < 2; kb++) {
            uint32_t Ah[2][4], Al[2][4];
#pragma unroll
            for (int mb = 0; mb < 2; mb++) {
                int m = mq * 32 + mb * 16 + lr;
                int uh = kb * 2 + uo;
                ldsm4(Ah[mb], aT + off128(m, uh));
                ldsm4(Al[mb], aT + off128(m, uh + 4));
            }
            int krow = kb * 16 + lr;
            uint32_t F1h[2][4], F1l[2][4], F3h[2][4], F3l[2][4];
#pragma unroll
            for (int nb = 0; nb < 2; nb++) {
                uint32_t so = off128(krow, nh * 4 + nb * 2 + uo);
                ldsm4t(F1h[nb], b1h + so); ldsm4t(F1l[nb], b1l + so);
                ldsm4t(F3h[nb], b3h + so); ldsm4t(F3l[nb], b3l + so);
            }
#pragma unroll
            for (int mb = 0; mb < 2; mb++)
#pragma unroll
                for (int nf = 0; nf < 4; nf++) {
                    int nb = nf >> 1, s = (nf & 1) * 2;
                    mma16816(acc1[mb][nf], Ah[mb], F1h[nb][s], F1h[nb][s + 1]);
                    mma16816(acc1[mb][nf], Ah[mb], F1l[nb][s], F1l[nb][s + 1]);
                    mma16816(acc1[mb][nf], Al[mb], F1h[nb][s], F1h[nb][s + 1]);
                    mma16816(acc3[mb][nf], Ah[mb], F3h[nb][s], F3h[nb][s + 1]);
                    mma16816(acc3[mb][nf], Ah[mb], F3l[nb][s], F3l[nb][s + 1]);
                    mma16816(acc3[mb][nf], Al[mb], F3h[nb][s], F3h[nb][s + 1]);
                }
        }
    }
    // epilogue: silu(acc1)*acc3 -> g_hact
    int gbase = g_base[e] + row0;
    int r0c = lane >> 2, cc = 2 * (lane & 3);
#pragma unroll
    for (int mb = 0; mb < 2; mb++)
#pragma unroll
        for (int nf = 0; nf < 4; nf++) {
            int m0 = mq * 32 + mb * 16 + r0c;
            int col = n0 + nh * 32 + nf * 8 + cc;
            if (m0 < rows) {
                float a0 = acc1[mb][nf][0], b0 = acc3[mb][nf][0];
                float a1 = acc1[mb][nf][1], b1 = acc3[mb][nf][1];
                float2 o;
                o.x = a0 / (1.f + __expf(-a0)) * b0;
                o.y = a1 / (1.f + __expf(-a1)) * b1;
                *(float2*)(g_hact + (size_t)(gbase + m0) * H_ + col) = o;
            }
            if (m0 + 8 < rows) {
                float a2 = acc1[mb][nf][2], b2 = acc3[mb][nf][2];
                float a3 = acc1[mb][nf][3], b3 = acc3[mb][nf][3];
                float2 o;
                o.x = a2 / (1.f + __expf(-a2)) * b2;
                o.y = a3 / (1.f + __expf(-a3)) * b3;
                *(float2*)(g_hact + (size_t)(gbase + m0 + 8) * H_ + col) = o;
            }
        }
}

// ============ ffn2: Y = hact @ w2, bf16 3-split mma.sync, scatter ============
// CTA: M=128, N=128. 8 warps = 4(M) x 2(N-half 64).
__global__ __launch_bounds__(256, 1) void ffn2_mma(const float* __restrict__ w2,
                                                   float* __restrict__ outF) {
    extern __shared__ char dyn[];
    __shared__ int toks[BM];
    __shared__ float wts[BM];
    int e = blockIdx.y >> 6, mt = blockIdx.y & 63;
    int cnt = g_cnt[e];
    int row0 = mt * BM;
    if (row0 >= cnt) return;
    int rows = min(BM, cnt - row0);
    int n0 = blockIdx.x * 128;
    int tid = threadIdx.x, wid = tid >> 5, lane = tid & 31;
    if (tid < BM) {
        int idx = e * T_ + row0 + tid;
        toks[tid] = (tid < rows) ? g_btok[idx] : 0;
        wts[tid] = (tid < rows) ? g_bwt[idx] : 0.f;
    }
    __syncthreads();
    uint32_t sb = (smem_u32(dyn) + 1023u) & ~1023u;

    int gbase = g_base[e] + row0;
    int am = tid >> 1, ak = (tid & 1) * 16;
    const float* ap = g_hact + (size_t)(gbase + min(am, rows - 1)) * H_ + ak;
    int bkr = tid >> 3, bnc = (tid & 7) * 16;
    const float* p2 = w2 + (size_t)e * H_ * D_ + (size_t)bkr * D_ + n0 + bnc;

    float4 ra[4], rb[4];
#pragma unroll
    for (int j = 0; j < 4; j++) ra[j] = *(const float4*)(ap + j * 4);
#pragma unroll
    for (int j = 0; j < 4; j++) rb[j] = *(const float4*)(p2 + j * 4);

    float acc[2][8][4];
#pragma unroll
    for (int a = 0; a < 2; a++)
#pragma unroll
        for (int b = 0; b < 8; b++)
#pragma unroll
            for (int q = 0; q < 4; q++) acc[a][b][q] = 0.f;

    int lr = (lane & 7) + ((lane >> 3) & 1) * 8;
    int uo = (lane >> 4) & 1;
    int mq = wid & 3, nh = wid >> 2;

    for (int c = 0; c < 32; c++) {
        uint32_t base = sb + (uint32_t)(c & 1) * 32768u;
        uint32_t aT = base, b2h = base + 16384u, b2l = base + 24576u;
        {
            uint32_t h[8], l[8];
            cvt2(ra[0].x, ra[0].y, h[0], l[0]); cvt2(ra[0].z, ra[0].w, h[1], l[1]);
            cvt2(ra[1].x, ra[1].y, h[2], l[2]); cvt2(ra[1].z, ra[1].w, h[3], l[3]);
            cvt2(ra[2].x, ra[2].y, h[4], l[4]); cvt2(ra[2].z, ra[2].w, h[5], l[5]);
            cvt2(ra[3].x, ra[3].y, h[6], l[6]); cvt2(ra[3].z, ra[3].w, h[7], l[7]);
            int u0 = ak >> 3;
            sts128u(aT + off128(am, u0),     h[0], h[1], h[2], h[3]);
            sts128u(aT + off128(am, u0 + 1), h[4], h[5], h[6], h[7]);
            sts128u(aT + off128(am, u0 + 4), l[0], l[1], l[2], l[3]);
            sts128u(aT + off128(am, u0 + 5), l[4], l[5], l[6], l[7]);
        }
        {
            uint32_t h[8], l[8];
            cvt2(rb[0].x, rb[0].y, h[0], l[0]); cvt2(rb[0].z, rb[0].w, h[1], l[1]);
            cvt2(rb[1].x, rb[1].y, h[2], l[2]); cvt2(rb[1].z, rb[1].w, h[3], l[3]);
            cvt2(rb[2].x, rb[2].y, h[4], l[4]); cvt2(rb[2].z, rb[2].w, h[5], l[5]);
            cvt2(rb[3].x, rb[3].y, h[6], l[6]); cvt2(rb[3].z, rb[3].w, h[7], l[7]);
            int u0 = bnc >> 3;
            sts128u(b2h + off256(bkr, u0),     h[0], h[1], h[2], h[3]);
            sts128u(b2h + off256(bkr, u0 + 1), h[4], h[5], h[6], h[7]);
            sts128u(b2l + off256(bkr, u0),     l[0], l[1], l[2], l[3]);
            sts128u(b2l + off256(bkr, u0 + 1), l[4], l[5], l[6], l[7]);
        }
        __syncthreads();
        if (c + 1 < 32) {
            const float* apn = ap + (c + 1) * 32;
#pragma unroll
            for (int j = 0; j < 4; j++) ra[j] = *(const float4*)(apn + j * 4);
            const float* qb = p2 + (size_t)(c + 1) * 32 * D_;
#pragma unroll
            for (int j = 0; j < 4; j++) rb[j] = *(const float4*)(qb + j * 4);
        }
#pragma unroll
        for (int kb = 0; kb < 2; kb++) {
            uint32_t Ah[2][4], Al[2][4];
#pragma unroll
            for (int mb = 0; mb < 2; mb++) {
                int m = mq * 32 + mb * 16 + lr;
                int uh = kb * 2 + uo;
                ldsm4(Ah[mb], aT + off128(m, uh));
                ldsm4(Al[mb], aT + off128(m, uh + 4));
            }
            int krow = kb * 16 + lr;
            uint32_t Fh[4][4], Fl[4][4];
#pragma unroll
            for (int nb = 0; nb < 4; nb++) {
                uint32_t so = off256(krow, nh * 8 + nb * 2 + uo);
                ldsm4t(Fh[nb], b2h + so);
                ldsm4t(Fl[nb], b2l + so);
            }
#pragma unroll
            for (int mb = 0; mb < 2; mb++)
#pragma unroll
                for (int nf = 0; nf < 8; nf++) {
                    int nb = nf >> 1, s = (nf & 1) * 2;
                    mma16816(acc[mb][nf], Ah[mb], Fh[nb][s], Fh[nb][s + 1]);
                    mma16816(acc[mb][nf], Ah[mb], Fl[nb][s], Fl[nb][s + 1]);
                    mma16816(acc[mb][nf], Al[mb], Fh[nb][s], Fh[nb][s + 1]);
                }
        }
    }
    // epilogue: scale + atomic scatter
    int r0c = lane >> 2, cc = 2 * (lane & 3);
#pragma unroll
    for (int mb = 0; mb < 2; mb++)
#pragma unroll
        for (int nf = 0; nf < 8; nf++) {
            int col = n0 + nh * 64 + nf * 8 + cc;
#pragma unroll
            for (int hrow = 0; hrow < 2; hrow++) {
                int m0 = mq * 32 + mb * 16 + r0c + hrow * 8;
                if (m0 < rows) {
                    int t = toks[m0];
                    float wt = wts[m0];
                    float v0 = wt * acc[mb][nf][hrow * 2];
                    float v1 = wt * acc[mb][nf][hrow * 2 + 1];
                    float* fo = outF + (size_t)t * D_ + col;
                    atomicAdd(fo, v0);
                    atomicAdd(fo + 1, v1);
                    if (g_nonpad[t]) {
                        float* mp = g_mean + (size_t)(e * B_ + (t >> 11)) * D_ + col;
                        atomicAdd(mp, v0);
                        atomicAdd(mp + 1, v1);
                    }
                }
            }
        }
}

// ---------------- classifier ----------------
__global__ void clf_kernel(const float* __restrict__ clf_w,
                           const float* __restrict__ clf_b,
                           float* __restrict__ outL) {
    __shared__ float dots[32];
    int w = threadIdx.x >> 5, lane = threadIdx.x & 31;
    const float* m = g_mean + (size_t)w * D_;
    float s = 0.f;
    for (int d = lane; d < D_; d += 32) s += m[d] * clf_w[d];
#pragma unroll
    for (int o = 16; o; o >>= 1) s += __shfl_xor_sync(0xffffffffu, s, o);
    if (lane == 0) dots[w] = s;
    __syncthreads();
    if (threadIdx.x < 32) {
        int e = threadIdx.x >> 2, b = threadIdx.x & 3;
        float c = 0.f;
        for (int ee = 0; ee <= e; ee++) c += dots[ee * 4 + b];
        outL[e * B_ + b] = c * g_invcnt[b] + clf_b[0];
    }
}

// ---------------- launch ----------------
extern "C" void kernel_launch(void* const* d_in, const int* in_sizes, int n_in,
                              void* d_out, int out_size) {
    int base = 4;
    if (n_in == 9 || (n_in > 3 && in_sizes[3] != 1)) base = 3;
    const float* x = (const float*)d_in[0];
    const unsigned char* pad = (const unsigned char*)d_in[1];
    const unsigned char* mid = (const unsigned char*)d_in[2];
    const float* gw = (const float*)d_in[base + 0];
    const float* w1 = (const float*)d_in[base + 1];
    const float* w2 = (const float*)d_in[base + 2];
    const float* w3 = (const float*)d_in[base + 3];
    const float* cw = (const float*)d_in[base + 4];
    const float* cb = (const float*)d_in[base + 5];
    float* out = (float*)d_out;

    float* out_final = out;
    float* out_logits = out + (size_t)T_ * D_;
    float* out_route = out + (size_t)T_ * D_ + E_ * B_;

    const int smem = 2 * 32768 + 1024;   // 66560
    cudaFuncSetAttribute(ffn1_mma, cudaFuncAttributeMaxDynamicSharedMemorySize, smem);
    cudaFuncSetAttribute(ffn2_mma, cudaFuncAttributeMaxDynamicSharedMemorySize, smem);

    cudaMemsetAsync(out_final, 0, (size_t)T_ * D_ * sizeof(float), 0);
    prep_kernel<<<1, 256>>>(pad, mid);
    gate_kernel<<<T_ / 8, 256>>>(x, gw, out_route);
    scan_kernel<<<1, 32>>>();
    ffn1_mma<<<dim3(H_ / 64, E_ * 64), 256, smem>>>(x, w1, w3);
    ffn2_mma<<<dim3(D_ / 128, E_ * 64), 256, smem>>>(w2, out_final);
    clf_kernel<<<1, 1024>>>(cw, cb, out_logits);
}